// round 16
// baseline (speedup 1.0000x reference)
#include <cuda_runtime.h>
#include <stdint.h>

// Problem constants
#define S_LEN   2048
#define PATCH   16
#define NWIN    2033            // S_LEN - PATCH + 1
#define ND      4
#define NCAND   (ND * NWIN)     // 8132
#define NB      32
#define NC      8
#define NROWS   (NB * NC)       // 256
#define NT      512
#define NWARP   (NT / 32)       // 16
#define CH      16              // chunk per thread (NT*CH = 8192 >= NCAND)
#define SXX_CONST 2728.0f       // sum_{k=0}^{31} (k-15.5)^2
#define CONV_ELEMS ((size_t)NROWS * ND * S_LEN)

// Scratch (static device globals; allocation-free).
// +16 zero pad: .bss zero-init, never written -> invalid gathers read 0.0f.
__device__ float    g_conv[CONV_ELEMS + 16];
__device__ uint32_t g_src[(size_t)NROWS * NCAND];

#define PAD_BYTE_OFF ((uint32_t)(CONV_ELEMS * 4))

// Padded smem index: +1 word every 16 -> lane stride 17 (coprime with 32
// banks) -> conflict-free scalar LDS for the chunked scan access pattern.
#define CVP(j) ((j) + ((j) >> 4))
#define CVP_WORDS CVP(ND * S_LEN)      // 8704

// affine bit-function f(s) = (s & a) ^ b, packed as a | (b<<1).
__device__ __forceinline__ int fcomb(int f1, int f2) {
    int a1 = f1 & 1, b1 = (f1 >> 1) & 1;
    int a2 = f2 & 1, b2 = (f2 >> 1) & 1;
    return (a1 & a2) | ((((b1 & a2) ^ b2)) << 1);
}

// ====================== fused conv + R^2 + scan ==========================
// One block per row. Conv from staged xs into padded smem (+ g_conv for the
// gather kernel), rolling-moment R^2 from conflict-free smem, warp-shuffle
// scans, compaction into packed gather codes (t:12 | d:2 | merged:1).
__global__ __launch_bounds__(NT) void k_rowscan(
    const float* __restrict__ seasonal,
    const float* __restrict__ conv_w,
    const float* __restrict__ conv_b)
{
    extern __shared__ float smf[];
    float* xs  = smf;                   // [S_LEN]
    float* cvp = xs + S_LEN;            // [CVP_WORDS], padded
    float* ws  = cvp + CVP_WORDS;       // [64]
    float* wb  = ws + 64;               // [4]
    int* warpf = (int*)(wb + 4);        // [NWARP]
    int* warpc = warpf + NWARP;         // [NWARP+1]

    const int row  = blockIdx.x;        // b*8 + c
    const int b    = row >> 3;
    const int c    = row & 7;
    const int tid  = threadIdx.x;
    const int lane = tid & 31;
    const int wid  = tid >> 5;

    // ---- stage weights + input row ----
    if (tid < 64) ws[tid] = conv_w[tid];
    if (tid < 4)  wb[tid] = conv_b[tid];
    for (int s = tid; s < S_LEN; s += NT)
        xs[s] = seasonal[((size_t)b * S_LEN + s) * NC + c];
    __syncthreads();

    // ---- dilated conv -> padded smem + global ----
    float* grow = g_conv + (size_t)row * ND * S_LEN;
    #pragma unroll
    for (int u = 0; u < (ND * S_LEN) / NT; u++) {
        int idx = u * NT + tid;
        int di  = idx >> 11;
        int t   = idx & (S_LEN - 1);
        int dil = 1 << di;
        float acc = wb[di];
        #pragma unroll
        for (int k = 0; k < PATCH; k++) {
            int j = t - (15 - k) * dil;
            float xv = (j >= 0) ? xs[j] : 0.0f;
            acc = fmaf(ws[di * PATCH + k], xv, acc);
        }
        cvp[CVP(idx)] = acc;
        grow[idx] = acc;
    }
    __syncthreads();

    const int base = tid * CH;

    // ---- can_merge bits: rolling window raw moments (from padded smem) ----
    uint32_t cmask = 0;
    {
        int d1 = base / NWIN;
        int t1 = base - d1 * NWIN;
        bool need_init = true;
        float S1 = 0.f, S2 = 0.f, M = 0.f;
        int rbase = d1 * S_LEN;
        #pragma unroll 1
        for (int q = 0; q < CH; q++) {
            int i = base + q;
            if (i >= NCAND - 1) break;
            if (t1 == NWIN - 1) {
                // cross-dilation pair: direct 32-element evaluation
                int w1 = d1 * S_LEN + t1;
                int w2 = (d1 + 1) * S_LEN;
                float s = 0.f, s2 = 0.f, sk = 0.f;
                #pragma unroll
                for (int k = 0; k < 16; k++) {
                    float y = cvp[CVP(w1 + k)];
                    s += y; s2 = fmaf(y, y, s2); sk = fmaf(y, (float)k, sk);
                }
                #pragma unroll
                for (int k = 0; k < 16; k++) {
                    float y = cvp[CVP(w2 + k)];
                    s += y; s2 = fmaf(y, y, s2); sk = fmaf(y, (float)(16 + k), sk);
                }
                float sxy = sk - 15.5f * s;
                float syy = s2 - s * s * (1.0f / 32.0f);
                float r2 = (sxy * sxy) / (SXX_CONST * syy);
                if (r2 >= 0.5f) cmask |= 1u << q;
                d1++; t1 = 0;
                rbase = d1 * S_LEN;
                need_init = true;
                continue;
            }
            if (need_init) {
                S1 = 0.f; S2 = 0.f; M = 0.f;
                #pragma unroll
                for (int k = 0; k < 16; k++) {
                    float y = cvp[CVP(rbase + t1 + k)];
                    S1 += y; S2 = fmaf(y, y, S2); M = fmaf(y, (float)k, M);
                }
                need_init = false;
            }
            float y0  = cvp[CVP(rbase + t1)];
            float y16 = cvp[CVP(rbase + t1 + 16)];
            float S1n = S1 - y0 + y16;
            float S2n = S2 - y0 * y0 + y16 * y16;
            float Mn  = M + 15.0f * y16 + y0 - S1;
            float sy  = S1 + S1n;
            float sy2 = S2 + S2n;
            float syk = M + Mn + 16.0f * S1n;
            float sxy = syk - 15.5f * sy;
            float syy = sy2 - sy * sy * (1.0f / 32.0f);
            float r2 = (sxy * sxy) / (SXX_CONST * syy);  // syy<=0 -> NaN -> false
            if (r2 >= 0.5f) cmask |= 1u << q;
            S1 = S1n; S2 = S2n; M = Mn;
            t1++;
        }
    }

    // ---- chunk function in closed form ----
    int f;
    {
        uint32_t t = (~cmask) & 0xFFFFu;
        if (t == 0) f = 1;
        else {
            int hz = 31 - __clz(t);
            int L  = 15 - hz;
            f = (L & 1) << 1;
        }
    }

    // ---- two-level non-commutative scan ----
    int finc = f;
    #pragma unroll
    for (int off = 1; off < 32; off <<= 1) {
        int g = __shfl_up_sync(0xffffffffu, finc, off);
        if (lane >= off) finc = fcomb(g, finc);
    }
    if (lane == 31) warpf[wid] = finc;
    __syncthreads();
    if (wid == 0) {
        int wf = (lane < NWARP) ? warpf[lane] : 1;
        #pragma unroll
        for (int off = 1; off < NWARP; off <<= 1) {
            int g = __shfl_up_sync(0xffffffffu, wf, off);
            if (lane >= off) wf = fcomb(g, wf);
        }
        if (lane < NWARP) warpf[lane] = wf;
    }
    __syncthreads();
    int fex = __shfl_up_sync(0xffffffffu, finc, 1);
    if (lane == 0) fex = 1;
    if (wid > 0)  fex = fcomb(warpf[wid - 1], fex);
    int s = (fex >> 1) & 1;

    // ---- emit merge/valid bits + counts ----
    uint32_t mbits = 0, vbits = 0;
    int cnt = 0;
    #pragma unroll
    for (int q = 0; q < CH; q++) {
        int i = base + q;
        if (i >= NCAND) break;
        int ci = (cmask >> q) & 1;
        int v  = s ^ 1;
        int mg = v & ci;
        mbits |= (uint32_t)mg << q;
        vbits |= (uint32_t)v  << q;
        cnt += v;
        s = mg;
    }

    // ---- two-level add scan ----
    int cinc = cnt;
    #pragma unroll
    for (int off = 1; off < 32; off <<= 1) {
        int g = __shfl_up_sync(0xffffffffu, cinc, off);
        if (lane >= off) cinc += g;
    }
    if (lane == 31) warpc[wid] = cinc;
    __syncthreads();
    if (wid == 0) {
        int wc = (lane < NWARP) ? warpc[lane] : 0;
        #pragma unroll
        for (int off = 1; off < NWARP; off <<= 1) {
            int g = __shfl_up_sync(0xffffffffu, wc, off);
            if (lane >= off) wc += g;
        }
        if (lane < NWARP) warpc[lane] = wc;
        if (lane == NWARP - 1) warpc[NWARP] = wc;
    }
    __syncthreads();
    int pos = __shfl_up_sync(0xffffffffu, cinc, 1);
    if (lane == 0) pos = 0;
    if (wid > 0) pos += warpc[wid - 1];

    // ---- compaction ----
    uint32_t* srow = g_src + (size_t)row * NCAND;
    {
        int d1 = base / NWIN;
        int t1 = base - d1 * NWIN;
        #pragma unroll 1
        for (int q = 0; q < CH; q++) {
            int i = base + q;
            if (i >= NCAND) break;
            if ((vbits >> q) & 1) {
                uint32_t code = (uint32_t)t1 | ((uint32_t)d1 << 12)
                              | (((mbits >> q) & 1u) << 14);
                srow[pos++] = code;
            }
            if (++t1 == NWIN) { t1 = 0; d1++; }
        }
    }
    int V = warpc[NWARP];
    for (int j = V + tid; j < NCAND; j += NT) srow[j] = 0xFFFFFFFFu;
}

#define ROWSCAN_SMEM ((S_LEN + CVP_WORDS + 64 + 4) * 4 + (NWARP + NWARP + 1) * 4)

// ============================ k_out (R8 measured-best) ===================
// out[b, n, k, c], c fastest. Block = 32 n x 16 k, each thread handles TWO
// independent n (ILP). Per-(c,n) absolute byte offsets precomputed in shared
// (merge flag in bit 31 of o2). Streamed stores keep conv table in L2.
__global__ __launch_bounds__(256) void k_out(float* __restrict__ out)
{
    __shared__ uint2 soff[8][32];     // [c][n_local] = (o1, o2|mergeflag)

    const int b   = blockIdx.y;
    const int n0  = blockIdx.x * 32;
    const int tid = threadIdx.x;

    {
        int cc = tid >> 5, nj = tid & 31;
        int n = n0 + nj;
        uint32_t cd = (n < NCAND)
                    ? __ldcs(&g_src[(size_t)(b * 8 + cc) * NCAND + n])
                    : 0xFFFFFFFFu;
        uint32_t o1, o2;
        if (cd == 0xFFFFFFFFu) {
            o1 = PAD_BYTE_OFF; o2 = PAD_BYTE_OFF;
        } else {
            int t1 = cd & 0xFFF;
            int d1 = (cd >> 12) & 3;
            uint32_t rbase = (uint32_t)((b * 8 + cc) * ND * S_LEN) * 4u;
            o1 = rbase + (uint32_t)(d1 * S_LEN + t1) * 4u;
            if (cd & (1u << 14)) {
                int t2 = t1 + 1, d2 = d1;
                if (t2 == NWIN) { t2 = 0; d2 = d1 + 1; }
                o2 = (rbase + (uint32_t)(d2 * S_LEN + t2) * 4u) | 0x80000000u;
            } else {
                o2 = o1;
            }
        }
        soff[cc][nj] = make_uint2(o1, o2);
    }
    __syncthreads();

    const int k  = tid & 15;
    const int nl = tid >> 4;          // 0..15
    const char* gp = (const char*)g_conv;
    const uint32_t k4 = (uint32_t)(k << 2);

    const int nA = n0 + nl;
    const int nB = n0 + nl + 16;

    float bufA[8], bufB[8];
    #pragma unroll
    for (int c = 0; c < 8; c++) {
        uint2 oa = soff[c][nl];
        uint2 ob = soff[c][nl + 16];
        float va1 = __ldg((const float*)(gp + oa.x + k4));
        float vb1 = __ldg((const float*)(gp + ob.x + k4));
        float va = va1, vb = vb1;
        if (oa.y & 0x80000000u) {
            float va2 = __ldg((const float*)(gp + (oa.y & 0x7FFFFFFFu) + k4));
            va = 0.5f * (va1 + va2);
        }
        if (ob.y & 0x80000000u) {
            float vb2 = __ldg((const float*)(gp + (ob.y & 0x7FFFFFFFu) + k4));
            vb = 0.5f * (vb1 + vb2);
        }
        bufA[c] = va;
        bufB[c] = vb;
    }

    if (nA < NCAND) {
        size_t obase = ((size_t)((b * NCAND + nA) * PATCH + k)) * 8;
        float4* o = (float4*)(out + obase);
        __stcs(o,     make_float4(bufA[0], bufA[1], bufA[2], bufA[3]));
        __stcs(o + 1, make_float4(bufA[4], bufA[5], bufA[6], bufA[7]));
    }
    if (nB < NCAND) {
        size_t obase = ((size_t)((b * NCAND + nB) * PATCH + k)) * 8;
        float4* o = (float4*)(out + obase);
        __stcs(o,     make_float4(bufB[0], bufB[1], bufB[2], bufB[3]));
        __stcs(o + 1, make_float4(bufB[4], bufB[5], bufB[6], bufB[7]));
    }
}

extern "C" void kernel_launch(void* const* d_in, const int* in_sizes, int n_in,
                              void* d_out, int out_size)
{
    const float* seasonal = (const float*)d_in[0];
    const float* cw       = (const float*)d_in[1];
    const float* cb       = (const float*)d_in[2];
    float* out = (float*)d_out;

    cudaFuncSetAttribute(k_rowscan, cudaFuncAttributeMaxDynamicSharedMemorySize,
                         ROWSCAN_SMEM);
    k_rowscan<<<NROWS, NT, ROWSCAN_SMEM>>>(seasonal, cw, cb);

    dim3 g((NCAND + 31) / 32, NB);
    k_out<<<g, 256>>>(out);
}

// round 17
// speedup vs baseline: 1.4819x; 1.4819x over previous
#include <cuda_runtime.h>
#include <stdint.h>

// Problem constants
#define S_LEN   2048
#define PATCH   16
#define NWIN    2033            // S_LEN - PATCH + 1
#define ND      4
#define NCAND   (ND * NWIN)     // 8132
#define NB      32
#define NC      8
#define NROWS   (NB * NC)       // 256
#define NT      512
#define NWARP   (NT / 32)       // 16
#define CH      16              // chunk per thread (NT*CH = 8192 >= NCAND)
#define SXX_CONST 2728.0f       // sum_{k=0}^{31} (k-15.5)^2
#define CONV_ELEMS ((size_t)NROWS * ND * S_LEN)

// Scratch (static device globals; allocation-free).
// +16 zero pad: .bss zero-init, never written -> invalid gathers read 0.0f,
// and vector-path overreads (up to +3 floats past a row) stay in bounds.
__device__ float    g_conv[CONV_ELEMS + 16];
__device__ uint32_t g_src[(size_t)NROWS * NCAND];

#define PAD_BYTE_OFF ((uint32_t)(CONV_ELEMS * 4))

// affine bit-function f(s) = (s & a) ^ b, packed as a | (b<<1).
__device__ __forceinline__ int fcomb(int f1, int f2) {
    int a1 = f1 & 1, b1 = (f1 >> 1) & 1;
    int a2 = f2 & 1, b2 = (f2 >> 1) & 1;
    return (a1 & a2) | ((((b1 & a2) ^ b2)) << 1);
}

// ============================ K_conv (R8, measured 10.3us) ===============
__global__ __launch_bounds__(NT) void k_conv(
    const float* __restrict__ seasonal,
    const float* __restrict__ conv_w,
    const float* __restrict__ conv_b)
{
    __shared__ float xs[S_LEN];
    __shared__ float ws[64];
    __shared__ float wb[4];

    const int row = blockIdx.x;          // b*8 + c
    const int b   = row >> 3;
    const int c   = row & 7;
    const int tid = threadIdx.x;

    if (tid < 64) ws[tid] = conv_w[tid];
    if (tid < 4)  wb[tid] = conv_b[tid];
    for (int s = tid; s < S_LEN; s += NT)
        xs[s] = seasonal[((size_t)b * S_LEN + s) * NC + c];
    __syncthreads();

    float* grow = g_conv + (size_t)row * ND * S_LEN;
    #pragma unroll
    for (int u = 0; u < (ND * S_LEN) / NT; u++) {
        int idx = u * NT + tid;
        int di  = idx >> 11;
        int t   = idx & (S_LEN - 1);
        int dil = 1 << di;
        float acc = wb[di];
        #pragma unroll
        for (int k = 0; k < PATCH; k++) {
            int j = t - (15 - k) * dil;
            float xv = (j >= 0) ? xs[j] : 0.0f;
            acc = fmaf(ws[di * PATCH + k], xv, acc);
        }
        grow[idx] = acc;
    }
}

// ---- register-resident 16-pair R^2 (alignment phase R = tb & 3) ----
template<int R>
__device__ __forceinline__ uint32_t pair_bits_reg(const float* z) {
    float S1 = 0.f, S2 = 0.f, M = 0.f;
    #pragma unroll
    for (int k = 0; k < 16; k++) {
        float y = z[R + k];
        S1 += y; S2 = fmaf(y, y, S2); M = fmaf(y, (float)k, M);
    }
    uint32_t bits = 0;
    #pragma unroll
    for (int q = 0; q < 16; q++) {
        float y0  = z[R + q];
        float y16 = z[R + q + 16];
        float S1n = S1 - y0 + y16;
        float S2n = S2 - y0 * y0 + y16 * y16;
        float Mn  = M + 15.0f * y16 + y0 - S1;
        float sy  = S1 + S1n;
        float sy2 = S2 + S2n;
        float syk = M + Mn + 16.0f * S1n;
        float sxy = syk - 15.5f * sy;
        float syy = sy2 - sy * sy * (1.0f / 32.0f);
        float r2 = (sxy * sxy) / (SXX_CONST * syy);  // syy<=0 -> NaN -> false
        if (r2 >= 0.5f) bits |= 1u << q;
        S1 = S1n; S2 = S2n; M = Mn;
    }
    return bits;
}

// ============================ K_scan =====================================
// R8 structure; the R^2 pass now uses 9 LDG.128 into registers for the 508
// non-boundary threads (each thread's 16 pairs need only y[tb..tb+31]).
__global__ __launch_bounds__(NT) void k_scan()
{
    __shared__ int warpf[NWARP];
    __shared__ int warpc[NWARP + 1];

    const int row  = blockIdx.x;
    const int tid  = threadIdx.x;
    const int lane = tid & 31;
    const int wid  = tid >> 5;

    const float* crow = g_conv + (size_t)row * ND * S_LEN;
    const int base = tid * CH;

    uint32_t cmask = 0;
    if (base < NCAND - 1) {
        int d  = base / NWIN;
        int tb = base - d * NWIN;
        if (tb + CH - 1 <= NWIN - 2) {
            // ---- vector path: 9 LDG.128, all math in registers ----
            const float* rowp = crow + d * S_LEN;
            int a0 = tb & ~3;
            int r0 = tb - a0;
            float z[36];
            const float4* vp = (const float4*)(rowp + a0);
            #pragma unroll
            for (int j = 0; j < 9; j++) {
                float4 v = __ldg(vp + j);
                z[4 * j]     = v.x;
                z[4 * j + 1] = v.y;
                z[4 * j + 2] = v.z;
                z[4 * j + 3] = v.w;
            }
            switch (r0) {
                case 0: cmask = pair_bits_reg<0>(z); break;
                case 1: cmask = pair_bits_reg<1>(z); break;
                case 2: cmask = pair_bits_reg<2>(z); break;
                default: cmask = pair_bits_reg<3>(z); break;
            }
        } else {
            // ---- scalar fallback: boundary chunks (4 threads/row) ----
            int d1 = d;
            int t1 = tb;
            bool need_init = true;
            float S1 = 0.f, S2 = 0.f, M = 0.f;
            const float* rowp = crow + d1 * S_LEN;
            #pragma unroll 1
            for (int q = 0; q < CH; q++) {
                int i = base + q;
                if (i >= NCAND - 1) break;
                if (t1 == NWIN - 1) {
                    const float* w1 = crow + d1 * S_LEN + t1;
                    const float* w2 = crow + (d1 + 1) * S_LEN;
                    float s = 0.f, s2 = 0.f, sk = 0.f;
                    #pragma unroll
                    for (int k = 0; k < 16; k++) {
                        float y = w1[k];
                        s += y; s2 = fmaf(y, y, s2); sk = fmaf(y, (float)k, sk);
                    }
                    #pragma unroll
                    for (int k = 0; k < 16; k++) {
                        float y = w2[k];
                        s += y; s2 = fmaf(y, y, s2); sk = fmaf(y, (float)(16 + k), sk);
                    }
                    float sxy = sk - 15.5f * s;
                    float syy = s2 - s * s * (1.0f / 32.0f);
                    float r2 = (sxy * sxy) / (SXX_CONST * syy);
                    if (r2 >= 0.5f) cmask |= 1u << q;
                    d1++; t1 = 0;
                    rowp = crow + d1 * S_LEN;
                    need_init = true;
                    continue;
                }
                if (need_init) {
                    S1 = 0.f; S2 = 0.f; M = 0.f;
                    #pragma unroll
                    for (int k = 0; k < 16; k++) {
                        float y = rowp[t1 + k];
                        S1 += y; S2 = fmaf(y, y, S2); M = fmaf(y, (float)k, M);
                    }
                    need_init = false;
                }
                float y0  = rowp[t1];
                float y16 = rowp[t1 + 16];
                float S1n = S1 - y0 + y16;
                float S2n = S2 - y0 * y0 + y16 * y16;
                float Mn  = M + 15.0f * y16 + y0 - S1;
                float sy  = S1 + S1n;
                float sy2 = S2 + S2n;
                float syk = M + Mn + 16.0f * S1n;
                float sxy = syk - 15.5f * sy;
                float syy = sy2 - sy * sy * (1.0f / 32.0f);
                float r2 = (sxy * sxy) / (SXX_CONST * syy);
                if (r2 >= 0.5f) cmask |= 1u << q;
                S1 = S1n; S2 = S2n; M = Mn;
                t1++;
            }
        }
    }

    // ---- chunk function in closed form ----
    int f;
    {
        uint32_t t = (~cmask) & 0xFFFFu;
        if (t == 0) f = 1;
        else {
            int hz = 31 - __clz(t);
            int L  = 15 - hz;
            f = (L & 1) << 1;
        }
    }

    // ---- two-level non-commutative scan ----
    int finc = f;
    #pragma unroll
    for (int off = 1; off < 32; off <<= 1) {
        int g = __shfl_up_sync(0xffffffffu, finc, off);
        if (lane >= off) finc = fcomb(g, finc);
    }
    if (lane == 31) warpf[wid] = finc;
    __syncthreads();
    if (wid == 0) {
        int wf = (lane < NWARP) ? warpf[lane] : 1;
        #pragma unroll
        for (int off = 1; off < NWARP; off <<= 1) {
            int g = __shfl_up_sync(0xffffffffu, wf, off);
            if (lane >= off) wf = fcomb(g, wf);
        }
        if (lane < NWARP) warpf[lane] = wf;
    }
    __syncthreads();
    int fex = __shfl_up_sync(0xffffffffu, finc, 1);
    if (lane == 0) fex = 1;
    if (wid > 0)  fex = fcomb(warpf[wid - 1], fex);
    int s = (fex >> 1) & 1;

    // ---- emit merge/valid bits + counts ----
    uint32_t mbits = 0, vbits = 0;
    int cnt = 0;
    #pragma unroll
    for (int q = 0; q < CH; q++) {
        int i = base + q;
        if (i >= NCAND) break;
        int ci = (cmask >> q) & 1;
        int v  = s ^ 1;
        int mg = v & ci;
        mbits |= (uint32_t)mg << q;
        vbits |= (uint32_t)v  << q;
        cnt += v;
        s = mg;
    }

    // ---- two-level add scan ----
    int cinc = cnt;
    #pragma unroll
    for (int off = 1; off < 32; off <<= 1) {
        int g = __shfl_up_sync(0xffffffffu, cinc, off);
        if (lane >= off) cinc += g;
    }
    if (lane == 31) warpc[wid] = cinc;
    __syncthreads();
    if (wid == 0) {
        int wc = (lane < NWARP) ? warpc[lane] : 0;
        #pragma unroll
        for (int off = 1; off < NWARP; off <<= 1) {
            int g = __shfl_up_sync(0xffffffffu, wc, off);
            if (lane >= off) wc += g;
        }
        if (lane < NWARP) warpc[lane] = wc;
        if (lane == NWARP - 1) warpc[NWARP] = wc;
    }
    __syncthreads();
    int pos = __shfl_up_sync(0xffffffffu, cinc, 1);
    if (lane == 0) pos = 0;
    if (wid > 0) pos += warpc[wid - 1];

    // ---- compaction: packed gather codes (t:12 | d:2 | merged:1) ----
    uint32_t* srow = g_src + (size_t)row * NCAND;
    {
        int d1 = base / NWIN;
        int t1 = base - d1 * NWIN;
        if (base >= NCAND) { d1 = 3; t1 = 0; }
        #pragma unroll 1
        for (int q = 0; q < CH; q++) {
            int i = base + q;
            if (i >= NCAND) break;
            if ((vbits >> q) & 1) {
                uint32_t code = (uint32_t)t1 | ((uint32_t)d1 << 12)
                              | (((mbits >> q) & 1u) << 14);
                srow[pos++] = code;
            }
            if (++t1 == NWIN) { t1 = 0; d1++; }
        }
    }
    int V = warpc[NWARP];
    for (int j = V + tid; j < NCAND; j += NT) srow[j] = 0xFFFFFFFFu;
}

// ============================ k_out (R8, measured best in-context) =======
__global__ __launch_bounds__(256) void k_out(float* __restrict__ out)
{
    __shared__ uint2 soff[8][32];     // [c][n_local] = (o1, o2|mergeflag)

    const int b   = blockIdx.y;
    const int n0  = blockIdx.x * 32;
    const int tid = threadIdx.x;

    {
        int cc = tid >> 5, nj = tid & 31;
        int n = n0 + nj;
        uint32_t cd = (n < NCAND)
                    ? __ldcs(&g_src[(size_t)(b * 8 + cc) * NCAND + n])
                    : 0xFFFFFFFFu;
        uint32_t o1, o2;
        if (cd == 0xFFFFFFFFu) {
            o1 = PAD_BYTE_OFF; o2 = PAD_BYTE_OFF;
        } else {
            int t1 = cd & 0xFFF;
            int d1 = (cd >> 12) & 3;
            uint32_t rbase = (uint32_t)((b * 8 + cc) * ND * S_LEN) * 4u;
            o1 = rbase + (uint32_t)(d1 * S_LEN + t1) * 4u;
            if (cd & (1u << 14)) {
                int t2 = t1 + 1, d2 = d1;
                if (t2 == NWIN) { t2 = 0; d2 = d1 + 1; }
                o2 = (rbase + (uint32_t)(d2 * S_LEN + t2) * 4u) | 0x80000000u;
            } else {
                o2 = o1;
            }
        }
        soff[cc][nj] = make_uint2(o1, o2);
    }
    __syncthreads();

    const int k  = tid & 15;
    const int nl = tid >> 4;          // 0..15
    const char* gp = (const char*)g_conv;
    const uint32_t k4 = (uint32_t)(k << 2);

    const int nA = n0 + nl;
    const int nB = n0 + nl + 16;

    float bufA[8], bufB[8];
    #pragma unroll
    for (int c = 0; c < 8; c++) {
        uint2 oa = soff[c][nl];
        uint2 ob = soff[c][nl + 16];
        float va1 = __ldg((const float*)(gp + oa.x + k4));
        float vb1 = __ldg((const float*)(gp + ob.x + k4));
        float va = va1, vb = vb1;
        if (oa.y & 0x80000000u) {
            float va2 = __ldg((const float*)(gp + (oa.y & 0x7FFFFFFFu) + k4));
            va = 0.5f * (va1 + va2);
        }
        if (ob.y & 0x80000000u) {
            float vb2 = __ldg((const float*)(gp + (ob.y & 0x7FFFFFFFu) + k4));
            vb = 0.5f * (vb1 + vb2);
        }
        bufA[c] = va;
        bufB[c] = vb;
    }

    if (nA < NCAND) {
        size_t obase = ((size_t)((b * NCAND + nA) * PATCH + k)) * 8;
        float4* o = (float4*)(out + obase);
        __stcs(o,     make_float4(bufA[0], bufA[1], bufA[2], bufA[3]));
        __stcs(o + 1, make_float4(bufA[4], bufA[5], bufA[6], bufA[7]));
    }
    if (nB < NCAND) {
        size_t obase = ((size_t)((b * NCAND + nB) * PATCH + k)) * 8;
        float4* o = (float4*)(out + obase);
        __stcs(o,     make_float4(bufB[0], bufB[1], bufB[2], bufB[3]));
        __stcs(o + 1, make_float4(bufB[4], bufB[5], bufB[6], bufB[7]));
    }
}

extern "C" void kernel_launch(void* const* d_in, const int* in_sizes, int n_in,
                              void* d_out, int out_size)
{
    const float* seasonal = (const float*)d_in[0];
    const float* cw       = (const float*)d_in[1];
    const float* cb       = (const float*)d_in[2];
    float* out = (float*)d_out;

    k_conv<<<NROWS, NT>>>(seasonal, cw, cb);
    k_scan<<<NROWS, NT>>>();

    dim3 g((NCAND + 31) / 32, NB);
    k_out<<<g, 256>>>(out);
}